// round 4
// baseline (speedup 1.0000x reference)
#include <cuda_runtime.h>
#include <math.h>

#define LDIM    1024
#define NROWS   32768          // B*D = 64*512
#define NGROUP  8192           // NROWS / 4
#define NBLK    148            // one block per SM, all resident
#define TPB     1024

// Scratch (allocation-free per harness rules)
__device__ float    g_att[NROWS];
__device__ float2   g_partial[NBLK];
__device__ unsigned g_ctr = 0;         // monotonic arrival counter (never reset)

__global__ void __launch_bounds__(TPB, 1)
fused_kernel(const float4* __restrict__ x,
             const float*  __restrict__ fc_w,
             const float*  __restrict__ fc_b,
             const float*  __restrict__ bn_gamma,
             const float*  __restrict__ bn_beta,
             const float*  __restrict__ conv_w,
             const float*  __restrict__ conv_b,
             float* __restrict__ out, int out_size) {
    __shared__ float sw[LDIM];
    __shared__ float s_ws[32], s_wq[32];
    __shared__ float s_mi[2];          // mean, inv_std

    const int t    = threadIdx.x;
    const int warp = t >> 5;
    const int lane = t & 31;
    const int bid  = blockIdx.x;

    // ---- build folded DCT weight vector: w[l] = sum_k fc_w[k]*C[k,l] ----
    {
        const float sqrt2L = sqrtf(2.0f / (float)LDIM);
        const float pi = 3.14159265358979323846f;
        float w0 = fc_w[0], w1 = fc_w[1], w2 = fc_w[2], w3 = fc_w[3], w4 = fc_w[4];
        int l = t;                       // TPB == LDIM
        float ph = pi * ((float)l + 0.5f) / (float)LDIM;
        float acc = w0 * sqrt2L * 0.70710678118654752f;
        acc += w1 * cosf(ph)        * sqrt2L;
        acc += w2 * cosf(2.0f * ph) * sqrt2L;
        acc += w3 * cosf(3.0f * ph) * sqrt2L;
        acc += w4 * cosf(4.0f * ph) * sqrt2L;
        sw[l] = acc;
    }
    __syncthreads();

    // ---- phase 1: groups of 4 rows per warp-iteration, deferred reduce ----
    const float4* wr = (const float4*)sw;
    const float fcb = fc_b[0];
    float bs = 0.0f, bq = 0.0f;        // lane0 accumulates block-stats partial

    for (int i = warp; bid + NBLK * i < NGROUP; i += 32) {
        int g = bid + NBLK * i;
        const float4* p = x + (size_t)g * LDIM;   // 4 rows * 256 float4 each

        float a0 = 0.0f, a1 = 0.0f, a2 = 0.0f, a3 = 0.0f;
#pragma unroll
        for (int j = 0; j < 8; j++) {
            int idx = j * 32 + lane;
            float4 w  = wr[idx];
            float4 v0 = __ldcs(p + idx);
            float4 v1 = __ldcs(p + idx + 256);
            float4 v2 = __ldcs(p + idx + 512);
            float4 v3 = __ldcs(p + idx + 768);
            a0 += v0.x * w.x + v0.y * w.y + v0.z * w.z + v0.w * w.w;
            a1 += v1.x * w.x + v1.y * w.y + v1.z * w.z + v1.w * w.w;
            a2 += v2.x * w.x + v2.y * w.y + v2.z * w.z + v2.w * w.w;
            a3 += v3.x * w.x + v3.y * w.y + v3.z * w.z + v3.w * w.w;
        }
#pragma unroll
        for (int off = 16; off; off >>= 1) {
            a0 += __shfl_xor_sync(0xffffffffu, a0, off);
            a1 += __shfl_xor_sync(0xffffffffu, a1, off);
            a2 += __shfl_xor_sync(0xffffffffu, a2, off);
            a3 += __shfl_xor_sync(0xffffffffu, a3, off);
        }
        if (lane == 0) {
            float t0 = a0 + fcb, t1 = a1 + fcb, t2 = a2 + fcb, t3 = a3 + fcb;
            int r = g * 4;
            g_att[r + 0] = t0;
            g_att[r + 1] = t1;
            g_att[r + 2] = t2;
            g_att[r + 3] = t3;
            bs += t0 + t1 + t2 + t3;
            bq += t0 * t0 + t1 * t1 + t2 * t2 + t3 * t3;
        }
    }

    // ---- block stats partial (fixed tree, deterministic) ----
    if (lane == 0) { s_ws[warp] = bs; s_wq[warp] = bq; }
    __syncthreads();
    if (warp == 0) {
        float s = s_ws[lane], q = s_wq[lane];
#pragma unroll
        for (int off = 16; off; off >>= 1) {
            s += __shfl_xor_sync(0xffffffffu, s, off);
            q += __shfl_xor_sync(0xffffffffu, q, off);
        }
        if (lane == 0) g_partial[bid] = make_float2(s, q);
    }

    // ---- grid barrier (148 blocks, 1/SM, all resident; monotonic counter) ----
    __threadfence();
    __syncthreads();
    if (t == 0) {
        unsigned old = atomicAdd(&g_ctr, 1u);
        unsigned target = old - (old % NBLK) + NBLK;
        unsigned c;
        do {
            asm volatile("ld.acquire.gpu.u32 %0, [%1];" : "=r"(c) : "l"(&g_ctr));
        } while (c < target);
    }
    __syncthreads();

    // ---- global stats (warp0 per block, fixed order -> deterministic) ----
    if (warp == 0) {
        float s = 0.0f, q = 0.0f;
#pragma unroll
        for (int j = 0; j < 5; j++) {
            int idx = lane + 32 * j;
            if (idx < NBLK) {
                float2 pv = __ldcg(&g_partial[idx]);
                s += pv.x;
                q += pv.y;
            }
        }
#pragma unroll
        for (int off = 16; off; off >>= 1) {
            s += __shfl_xor_sync(0xffffffffu, s, off);
            q += __shfl_xor_sync(0xffffffffu, q, off);
        }
        if (lane == 0) {
            float mean = s / (float)NROWS;
            float var  = q / (float)NROWS - mean * mean;
            s_mi[0] = mean;
            s_mi[1] = rsqrtf(var + 1e-5f);
        }
    }
    __syncthreads();

    // ---- epilogue: BN + exact GELU + sigmoid; write both output halves ----
    {
        int i = bid * TPB + t;          // blocks 0..31 cover all 32768 rows
        if (i < NROWS) {
            float a = (__ldcg(&g_att[i]) - s_mi[0]) * s_mi[1] * bn_gamma[0] + bn_beta[0];
            a = 0.5f * a * (1.0f + erff(a * 0.70710678118654752f));
            float z = a * conv_w[0] + conv_b[0];
            float gt = 1.0f / (1.0f + expf(-z));
            out[i] = gt;
            if (out_size >= 2 * NROWS) out[i + NROWS] = gt;
        }
    }
}

// ---------------------------------------------------------------------------
// Inputs (metadata order): x[64,512,1024] f32, fc_w[5], fc_b[1],
//                          bn_gamma[1], bn_beta[1], conv_w[1], conv_b[1]
// Output: (att1, att2) each [B, D, 1] -> 2*32768 f32
// ---------------------------------------------------------------------------
extern "C" void kernel_launch(void* const* d_in, const int* in_sizes, int n_in,
                              void* d_out, int out_size) {
    const float4* x        = (const float4*)d_in[0];
    const float*  fc_w     = (const float*)d_in[1];
    const float*  fc_b     = (const float*)d_in[2];
    const float*  bn_gamma = (const float*)d_in[3];
    const float*  bn_beta  = (const float*)d_in[4];
    const float*  conv_w   = (const float*)d_in[5];
    const float*  conv_b   = (const float*)d_in[6];
    float* out = (float*)d_out;

    fused_kernel<<<NBLK, TPB>>>(x, fc_w, fc_b, bn_gamma, bn_beta,
                                conv_w, conv_b, out, out_size);
}

// round 5
// speedup vs baseline: 1.0477x; 1.0477x over previous
#include <cuda_runtime.h>
#include <math.h>

#define LDIM    1024
#define NROWS   32768          // B*D = 64*512
#define NBLK    148            // one block per SM, all resident
#define TPB     1024

// Scratch (allocation-free per harness rules)
__device__ float    g_att[NROWS];
__device__ float2   g_partial[NBLK];
__device__ unsigned g_ctr = 0;         // monotonic arrival counter (never reset)

__global__ void __launch_bounds__(TPB, 1)
fused_kernel(const float4* __restrict__ x,
             const float*  __restrict__ fc_w,
             const float*  __restrict__ fc_b,
             const float*  __restrict__ bn_gamma,
             const float*  __restrict__ bn_beta,
             const float*  __restrict__ conv_w,
             const float*  __restrict__ conv_b,
             float* __restrict__ out, int out_size) {
    __shared__ float sw[LDIM];
    __shared__ float s_ws[32], s_wq[32];
    __shared__ float s_mi[2];          // mean, inv_std

    const int t    = threadIdx.x;
    const int warp = t >> 5;
    const int lane = t & 31;
    const int bid  = blockIdx.x;

    // ---- build folded DCT weight vector: w[l] = sum_k fc_w[k]*C[k,l] ----
    {
        const float sqrt2L = sqrtf(2.0f / (float)LDIM);
        const float pi = 3.14159265358979323846f;
        float w0 = fc_w[0], w1 = fc_w[1], w2 = fc_w[2], w3 = fc_w[3], w4 = fc_w[4];
        int l = t;                       // TPB == LDIM
        float ph = pi * ((float)l + 0.5f) / (float)LDIM;
        float acc = w0 * sqrt2L * 0.70710678118654752f;
        acc += w1 * cosf(ph)        * sqrt2L;
        acc += w2 * cosf(2.0f * ph) * sqrt2L;
        acc += w3 * cosf(3.0f * ph) * sqrt2L;
        acc += w4 * cosf(4.0f * ph) * sqrt2L;
        sw[l] = acc;
    }
    __syncthreads();

    // ---- phase 1: one row per warp-iteration, software-pipelined reduce ----
    // Row i's loads are issued BEFORE row i-1's shuffle reduce, so the 5-deep
    // shfl chain is hidden under DRAM latency of the in-flight loads.
    const float4* wr = (const float4*)sw;
    const float fcb = fc_b[0];
    float bs = 0.0f, bq = 0.0f;        // lane0 stats partial
    float accPrev = 0.0f;
    int   rowPrev = -1;

    for (int i = warp; bid + NBLK * i < NROWS; i += 32) {
        int row = bid + NBLK * i;
        const float4* p = x + (size_t)row * (LDIM / 4);

        // issue this row's 8 loads (independent of the reduce below)
        float4 v0 = __ldcs(p + 0 * 32 + lane);
        float4 v1 = __ldcs(p + 1 * 32 + lane);
        float4 v2 = __ldcs(p + 2 * 32 + lane);
        float4 v3 = __ldcs(p + 3 * 32 + lane);
        float4 v4 = __ldcs(p + 4 * 32 + lane);
        float4 v5 = __ldcs(p + 5 * 32 + lane);
        float4 v6 = __ldcs(p + 6 * 32 + lane);
        float4 v7 = __ldcs(p + 7 * 32 + lane);

        // reduce PREVIOUS row while the loads above are in flight
        if (rowPrev >= 0) {
            float a = accPrev;
#pragma unroll
            for (int off = 16; off; off >>= 1)
                a += __shfl_xor_sync(0xffffffffu, a, off);
            if (lane == 0) {
                float v = a + fcb;
                g_att[rowPrev] = v;
                bs += v;
                bq += v * v;
            }
        }

        // consume this row's loads
        float acc = 0.0f;
        {
            float4 w;
            w = wr[0 * 32 + lane]; acc += v0.x*w.x + v0.y*w.y + v0.z*w.z + v0.w*w.w;
            w = wr[1 * 32 + lane]; acc += v1.x*w.x + v1.y*w.y + v1.z*w.z + v1.w*w.w;
            w = wr[2 * 32 + lane]; acc += v2.x*w.x + v2.y*w.y + v2.z*w.z + v2.w*w.w;
            w = wr[3 * 32 + lane]; acc += v3.x*w.x + v3.y*w.y + v3.z*w.z + v3.w*w.w;
            w = wr[4 * 32 + lane]; acc += v4.x*w.x + v4.y*w.y + v4.z*w.z + v4.w*w.w;
            w = wr[5 * 32 + lane]; acc += v5.x*w.x + v5.y*w.y + v5.z*w.z + v5.w*w.w;
            w = wr[6 * 32 + lane]; acc += v6.x*w.x + v6.y*w.y + v6.z*w.z + v6.w*w.w;
            w = wr[7 * 32 + lane]; acc += v7.x*w.x + v7.y*w.y + v7.z*w.z + v7.w*w.w;
        }
        accPrev = acc;
        rowPrev = row;
    }

    // drain the pipeline: reduce the final row
    if (rowPrev >= 0) {
        float a = accPrev;
#pragma unroll
        for (int off = 16; off; off >>= 1)
            a += __shfl_xor_sync(0xffffffffu, a, off);
        if (lane == 0) {
            float v = a + fcb;
            g_att[rowPrev] = v;
            bs += v;
            bq += v * v;
        }
    }

    // ---- block stats partial (fixed tree, deterministic) ----
    if (lane == 0) { s_ws[warp] = bs; s_wq[warp] = bq; }
    __syncthreads();
    if (warp == 0) {
        float s = s_ws[lane], q = s_wq[lane];
#pragma unroll
        for (int off = 16; off; off >>= 1) {
            s += __shfl_xor_sync(0xffffffffu, s, off);
            q += __shfl_xor_sync(0xffffffffu, q, off);
        }
        if (lane == 0) g_partial[bid] = make_float2(s, q);
    }

    // ---- grid barrier (148 blocks, 1/SM, all resident; monotonic counter) ----
    __threadfence();
    __syncthreads();
    if (t == 0) {
        unsigned old = atomicAdd(&g_ctr, 1u);
        unsigned target = old - (old % NBLK) + NBLK;
        unsigned c;
        do {
            asm volatile("ld.acquire.gpu.u32 %0, [%1];" : "=r"(c) : "l"(&g_ctr));
        } while (c < target);
    }
    __syncthreads();

    // ---- global stats (warp0 per block, fixed order -> deterministic) ----
    if (warp == 0) {
        float s = 0.0f, q = 0.0f;
#pragma unroll
        for (int j = 0; j < 5; j++) {
            int idx = lane + 32 * j;
            if (idx < NBLK) {
                float2 pv = __ldcg(&g_partial[idx]);
                s += pv.x;
                q += pv.y;
            }
        }
#pragma unroll
        for (int off = 16; off; off >>= 1) {
            s += __shfl_xor_sync(0xffffffffu, s, off);
            q += __shfl_xor_sync(0xffffffffu, q, off);
        }
        if (lane == 0) {
            float mean = s / (float)NROWS;
            float var  = q / (float)NROWS - mean * mean;
            s_mi[0] = mean;
            s_mi[1] = rsqrtf(var + 1e-5f);
        }
    }
    __syncthreads();

    // ---- epilogue: BN + exact GELU + sigmoid; write both output halves ----
    {
        int i = bid * TPB + t;          // 148*1024 threads cover 32768 rows
        if (i < NROWS) {
            float a = (__ldcg(&g_att[i]) - s_mi[0]) * s_mi[1] * bn_gamma[0] + bn_beta[0];
            a = 0.5f * a * (1.0f + erff(a * 0.70710678118654752f));
            float z = a * conv_w[0] + conv_b[0];
            float gt = 1.0f / (1.0f + expf(-z));
            out[i] = gt;
            if (out_size >= 2 * NROWS) out[i + NROWS] = gt;
        }
    }
}

// ---------------------------------------------------------------------------
// Inputs (metadata order): x[64,512,1024] f32, fc_w[5], fc_b[1],
//                          bn_gamma[1], bn_beta[1], conv_w[1], conv_b[1]
// Output: (att1, att2) each [B, D, 1] -> 2*32768 f32
// ---------------------------------------------------------------------------
extern "C" void kernel_launch(void* const* d_in, const int* in_sizes, int n_in,
                              void* d_out, int out_size) {
    const float4* x        = (const float4*)d_in[0];
    const float*  fc_w     = (const float*)d_in[1];
    const float*  fc_b     = (const float*)d_in[2];
    const float*  bn_gamma = (const float*)d_in[3];
    const float*  bn_beta  = (const float*)d_in[4];
    const float*  conv_w   = (const float*)d_in[5];
    const float*  conv_b   = (const float*)d_in[6];
    float* out = (float*)d_out;

    fused_kernel<<<NBLK, TPB>>>(x, fc_w, fc_b, bn_gamma, bn_beta,
                                conv_w, conv_b, out, out_size);
}

// round 6
// speedup vs baseline: 1.0489x; 1.0011x over previous
#include <cuda_runtime.h>
#include <math.h>

#define LDIM    1024
#define NROWS   32768      // B*D = 64*512
#define NBLK_A  4096       // NROWS / 8 rows-per-block
#define NBLK_B  32         // 32 * 1024 = NROWS

// Scratch (allocation-free per harness rules)
__device__ float  g_att[NROWS];
__device__ float2 g_partial[NBLK_A];

// ---------------------------------------------------------------------------
// Kernel A: fused w-build (Chebyshev) + per-row dot + per-block stats partial.
// 4096 blocks x 256 threads; one warp per 1024-float row (8 rows/block).
// Many small blocks -> HW scheduler balances DRAM traffic; high occupancy.
// ---------------------------------------------------------------------------
__global__ void __launch_bounds__(256) dot_kernel(const float4* __restrict__ x,
                                                  const float* __restrict__ fc_w,
                                                  const float* __restrict__ fc_b) {
    __shared__ float sw[LDIM];
    __shared__ float s_att[8];
    int t = threadIdx.x;

    // w[l] = sqrt(2/L) * (fc_w0/sqrt2 + sum_{k=1..4} fc_wk * cos(k*ph)),
    // cos(k*ph) via Chebyshev recurrence: one cosf per element.
    {
        const float sqrt2L = sqrtf(2.0f / (float)LDIM);
        const float pi = 3.14159265358979323846f;
        float w0 = fc_w[0] * 0.70710678118654752f;
        float w1 = fc_w[1], w2 = fc_w[2], w3 = fc_w[3], w4 = fc_w[4];
#pragma unroll
        for (int j = 0; j < 4; j++) {
            int l = t + j * 256;
            float ph = pi * ((float)l + 0.5f) / (float)LDIM;
            float c1 = cosf(ph);
            float c2 = 2.0f * c1 * c1 - 1.0f;
            float c3 = 2.0f * c1 * c2 - c1;
            float c4 = 2.0f * c1 * c3 - c2;
            sw[l] = sqrt2L * (w0 + w1 * c1 + w2 * c2 + w3 * c3 + w4 * c4);
        }
    }
    __syncthreads();

    int warp = t >> 5;
    int lane = t & 31;
    int row  = blockIdx.x * 8 + warp;

    const float4* xr = x + (size_t)row * (LDIM / 4);
    const float4* wr = (const float4*)sw;

    float acc = 0.0f;
#pragma unroll
    for (int j = 0; j < 8; j++) {
        int idx = j * 32 + lane;
        float4 v = __ldcs(xr + idx);
        float4 w = wr[idx];
        acc += v.x * w.x + v.y * w.y + v.z * w.z + v.w * w.w;
    }
#pragma unroll
    for (int off = 16; off; off >>= 1)
        acc += __shfl_xor_sync(0xffffffffu, acc, off);

    float att = acc + fc_b[0];
    if (lane == 0) {
        g_att[row] = att;
        s_att[warp] = att;
    }
    __syncthreads();

    if (t == 0) {
        float s = 0.0f, q = 0.0f;
#pragma unroll
        for (int i = 0; i < 8; i++) {
            float v = s_att[i];
            s += v;
            q += v * v;
        }
        g_partial[blockIdx.x] = make_float2(s, q);
    }
}

// ---------------------------------------------------------------------------
// Kernel B: redundant per-block stats reduction (warp-parallel, 2 syncs)
// + BN + exact GELU + sigmoid gate. 32 blocks x 1024 threads, 1 row/thread.
// ---------------------------------------------------------------------------
__global__ void __launch_bounds__(1024) epilogue_kernel(float* __restrict__ out,
                                                        const float* __restrict__ bn_gamma,
                                                        const float* __restrict__ bn_beta,
                                                        const float* __restrict__ conv_w,
                                                        const float* __restrict__ conv_b,
                                                        int out_size) {
    __shared__ float s_ws[32], s_wq[32];
    __shared__ float s_mi[2];
    int t    = threadIdx.x;
    int warp = t >> 5;
    int lane = t & 31;

    // Each thread: 4 partials (fixed order); warp reduce; warp0 final reduce.
    float s = 0.0f, q = 0.0f;
#pragma unroll
    for (int j = 0; j < NBLK_A / 1024; j++) {
        float2 p = __ldcg(&g_partial[t + j * 1024]);
        s += p.x;
        q += p.y;
    }
#pragma unroll
    for (int off = 16; off; off >>= 1) {
        s += __shfl_xor_sync(0xffffffffu, s, off);
        q += __shfl_xor_sync(0xffffffffu, q, off);
    }
    if (lane == 0) { s_ws[warp] = s; s_wq[warp] = q; }
    __syncthreads();
    if (warp == 0) {
        float ss = s_ws[lane], qq = s_wq[lane];
#pragma unroll
        for (int off = 16; off; off >>= 1) {
            ss += __shfl_xor_sync(0xffffffffu, ss, off);
            qq += __shfl_xor_sync(0xffffffffu, qq, off);
        }
        if (lane == 0) {
            float mean = ss / (float)NROWS;
            float var  = qq / (float)NROWS - mean * mean;
            s_mi[0] = mean;
            s_mi[1] = rsqrtf(var + 1e-5f);
        }
    }
    __syncthreads();

    int i = blockIdx.x * 1024 + t;      // 32 * 1024 == NROWS
    float a = (__ldcg(&g_att[i]) - s_mi[0]) * s_mi[1] * bn_gamma[0] + bn_beta[0];
    a = 0.5f * a * (1.0f + erff(a * 0.70710678118654752f));
    float z = a * conv_w[0] + conv_b[0];
    float g = 1.0f / (1.0f + expf(-z));
    out[i] = g;
    if (out_size >= 2 * NROWS) out[i + NROWS] = g;
}

// ---------------------------------------------------------------------------
// Inputs (metadata order): x[64,512,1024] f32, fc_w[5], fc_b[1],
//                          bn_gamma[1], bn_beta[1], conv_w[1], conv_b[1]
// Output: (att1, att2) each [B, D, 1] -> 2*32768 f32
// ---------------------------------------------------------------------------
extern "C" void kernel_launch(void* const* d_in, const int* in_sizes, int n_in,
                              void* d_out, int out_size) {
    const float4* x        = (const float4*)d_in[0];
    const float*  fc_w     = (const float*)d_in[1];
    const float*  fc_b     = (const float*)d_in[2];
    const float*  bn_gamma = (const float*)d_in[3];
    const float*  bn_beta  = (const float*)d_in[4];
    const float*  conv_w   = (const float*)d_in[5];
    const float*  conv_b   = (const float*)d_in[6];
    float* out = (float*)d_out;

    dot_kernel<<<NBLK_A, 256>>>(x, fc_w, fc_b);
    epilogue_kernel<<<NBLK_B, 1024>>>(out, bn_gamma, bn_beta, conv_w, conv_b, out_size);
}